// round 13
// baseline (speedup 1.0000x reference)
#include <cuda_runtime.h>
#include <cuda_bf16.h>
#include <cstdint>

#define THREADS 512
#define RCOLS   224
#define MSTR2   228     // Ms row stride in float2 (mod 16 == 4 -> conflict-free LDS.64)
#define XSTR    68      // Xs row stride (mod 32 == 4 -> conflict-free A frags)
#define GSTR    68
#define W1STR2  68      // W1 row stride in float2 (mod 16 == 4)
#define TSTR    228     // t staging row stride (16 rows per half)

// group-local smem block sizes (floats)
#define GRP_FLOATS (2176 + 2176 + 3648 + 2*288 + 2*32 + 128)   // 8768
#define MS_FLOATS  (32 * MSTR2 * 2)                             // 14592
#define W1_FLOATS  (32 * W1STR2 * 2)                            // 4352
#define CONST_OFF  (MS_FLOATS + W1_FLOATS + 4 * GRP_FLOATS)     // 54016

// Precomputed fused weight M, row-pair packed:
//   g_M[(prow*224 + col)*2 + slot],  prow=(k>>3)*4+(k&3), slot=(k>>2)&1
// bias row c[256] (fp32), W1 packed the same way (64 cols).
__device__ __align__(16) float g_M[32 * 224 * 2];
__device__ __align__(16) float g_c[256];
__device__ __align__(16) float g_W1[32 * 64 * 2];

__device__ __forceinline__ uint32_t f2tf32(float f) {
    uint32_t u;
    asm("cvt.rna.tf32.f32 %0, %1;" : "=r"(u) : "f"(f));
    return u;
}

// ---------------------------------------------------------------------------
// Precompute: c-loop split 4-way across threads, smem reduce.
// Blocks 0..64: M rows (64 = bias row). Blocks 65..68: W1 tf32 conversion.
// ---------------------------------------------------------------------------
__global__ __launch_bounds__(1024)
void precompute_kernel(const float* __restrict__ exp_w,
                       const float* __restrict__ exp_b,
                       const float* __restrict__ rad_w2,
                       const float* __restrict__ rad_b2,
                       const float* __restrict__ pw0,
                       const float* __restrict__ pw1,
                       const float* __restrict__ pw2,
                       const float* __restrict__ rad_w1) {
    int k = blockIdx.x;
    int tid = threadIdx.x;

    if (k >= 65) {                       // W1 conversion: 4 blocks x 1024
        int i = (k - 65) * 1024 + tid;
        if (i < 64 * 64) {
            int kk = i >> 6, col = i & 63;
            int prow = (kk >> 3) * 4 + (kk & 3);
            int slot = (kk >> 2) & 1;
            g_W1[prow * 128 + col * 2 + slot] = __uint_as_float(f2tf32(rad_w1[i]));
        }
        return;
    }

    __shared__ float s_s[128];
    __shared__ float s_w[384];
    __shared__ float part[4][256];

    if (tid < 128) s_s[tid] = exp_w[tid] + exp_b[tid];
    if (tid >= 128 && tid < 512) {
        int i = tid - 128;
        s_w[i] = (k < 64) ? rad_w2[k * 384 + i] : rad_b2[i];
    }
    __syncthreads();

    const int cs  = tid >> 8;    // 0..3: c chunk
    const int col = tid & 255;   // 0..255
    float acc = 0.f;
    if (col < RCOLS) {
        const float* P;
        int d, woff, pstride;
        if (col < 128)      { P = pw0; d = col;       woff = 0;   pstride = 128; }
        else if (col < 192) { P = pw1; d = col - 128; woff = 128; pstride = 64;  }
        else                { P = pw2; d = col - 192; woff = 256; pstride = 32;  }
        const int c0 = cs * 32;
        #pragma unroll 8
        for (int c = c0; c < c0 + 32; c++)
            acc += s_w[woff + c] * s_s[c] * __ldg(&P[c * pstride + d]);
    }
    part[cs][col] = acc;
    __syncthreads();

    if (tid < 256) {
        float sum = (part[0][tid] + part[1][tid]) + (part[2][tid] + part[3][tid]);
        sum *= 0.25f;   // 1/sqrt(AVG_AGG)
        if (k < 64) {
            if (tid < RCOLS) {
                int prow = (k >> 3) * 4 + (k & 3);
                int slot = (k >> 2) & 1;
                g_M[(prow * 224 + tid) * 2 + slot] = __uint_as_float(f2tf32(sum));
            }
        } else {
            g_c[tid] = sum;
        }
    }
}

// ---------------------------------------------------------------------------
__device__ __forceinline__ void red4(float* p, float a, float b, float c, float d) {
    asm volatile("red.global.add.v4.f32 [%0], {%1, %2, %3, %4};"
                 :: "l"(p), "f"(a), "f"(b), "f"(c), "f"(d) : "memory");
}

__device__ __forceinline__ void cp_async16(void* smem_ptr, const void* gmem) {
    uint32_t s = (uint32_t)__cvta_generic_to_shared(smem_ptr);
    asm volatile("cp.async.cg.shared.global [%0], [%1], 16;" :: "r"(s), "l"(gmem));
}
__device__ __forceinline__ void cp_async16_zfill(void* smem_ptr, const void* gmem, int srcsz) {
    uint32_t s = (uint32_t)__cvta_generic_to_shared(smem_ptr);
    asm volatile("cp.async.cg.shared.global [%0], [%1], 16, %2;"
                 :: "r"(s), "l"(gmem), "r"(srcsz));
}

__device__ __forceinline__ void mma_tf32(float d[4], const uint32_t a[4],
                                         uint32_t b0, uint32_t b1) {
    asm volatile(
        "mma.sync.aligned.m16n8k8.row.col.f32.tf32.tf32.f32 "
        "{%0,%1,%2,%3}, {%4,%5,%6,%7}, {%8,%9}, {%0,%1,%2,%3};"
        : "+f"(d[0]), "+f"(d[1]), "+f"(d[2]), "+f"(d[3])
        : "r"(a[0]), "r"(a[1]), "r"(a[2]), "r"(a[3]), "r"(b0), "r"(b1));
}

// group barrier (named): 128 threads of group g
__device__ __forceinline__ void barg(int g) {
    asm volatile("bar.sync %0, %1;" :: "r"(g + 1), "r"(128) : "memory");
}

// ---------------------------------------------------------------------------
// per-edge scatter body (fast = no bounds/clamp checks)
// ---------------------------------------------------------------------------
template <bool FAST>
__device__ __forceinline__ void scatter_edge(const float* __restrict__ te,
                                             const float* __restrict__ sh,
                                             float* __restrict__ base,
                                             const float4 b0v, int l)
{
    const float s0 = sh[0];

    // region 0: cols 0..127, one red4 per lane
    {
        float4 v = *(const float4*)&te[l * 4];
        red4(base + l * 4,
             fmaf(s0, v.x, b0v.x), fmaf(s0, v.y, b0v.y),
             fmaf(s0, v.z, b0v.z), fmaf(s0, v.w, b0v.w));
    }
    // regions 1+2 merged: 88 quad-items in 3 rounds
    #pragma unroll
    for (int r = 0; r < 3; r++) {
        int j = l + r * 32;
        if (j < 88) {
            int  r2   = (j >= 48);
            int  jj   = r2 ? (j - 48) : j;
            int  pidx = 4 * jj;
            int  q    = r2 ? ((pidx * 0x3334) >> 16)
                           : ((pidx * 0x5556) >> 16);
            int  mod  = r2 ? 5 : 3;
            int  m    = pidx - mod * q;
            const float* tb_ = te + (r2 ? 192 : 128);
            int  qb = q + 1;
            if (!FAST) { if (r2 && qb > 31) qb = 31; }
            float ta  = tb_[q];
            float tbv = tb_[qb];   // FAST: q=31 only when unused; reads row pad
            const float* shb = sh + (r2 ? 4 : 1);
            float v[4];
            #pragma unroll
            for (int ii = 0; ii < 4; ii++) {
                int mi = m + ii;
                int f  = (mi >= mod);
                float sv = shb[mi - mod * f];
                v[ii] = (f ? tbv : ta) * sv;
            }
            red4(base + (r2 ? 320 : 128) + pidx, v[0], v[1], v[2], v[3]);
        }
    }
}

// ---------------------------------------------------------------------------
// Persistent kernel, FOUR independent 128-thread warp-groups per CTA.
// Each group owns a stream of 32-edge tiles; groups overlap GEMM vs scatter.
// ---------------------------------------------------------------------------
__global__ __launch_bounds__(THREADS, 1)
void edge_main_kernel(const float* __restrict__ edge_attr,
                      const float* __restrict__ edge_scalars,
                      const int*   __restrict__ edge_dst,
                      const float* __restrict__ rad_b1,
                      const float* __restrict__ rad_gamma,
                      const float* __restrict__ rad_beta,
                      const float* __restrict__ proj_b0,
                      float* __restrict__ out,
                      int E, int nTiles)
{
    extern __shared__ float smem[];
    float* Ms   = smem;                     // 14592 (32 x 228 float2)
    float* W1s  = Ms + MS_FLOATS;           // 4352  (32 x 68 float2)
    // constants
    float* b1s  = smem + CONST_OFF;         // 64
    float* gms  = b1s + 64;                 // 64
    float* bts  = gms + 64;                 // 64
    float* cS   = bts + 64;                 // 256
    float* b0s  = cS + 256;                 // 128

    const int tid = threadIdx.x;
    const int g   = tid >> 7;        // warp-group 0..3
    const int gt  = tid & 127;       // thread-in-group
    const int l   = tid & 31;
    const int wg  = (tid >> 5) & 3;  // warp-in-group 0..3

    // group-local buffers
    float* GB   = smem + MS_FLOATS + W1_FLOATS + g * GRP_FLOATS;
    float* Xs   = GB;                       // 32*68 = 2176
    float* Gs   = Xs + 2176;                // 32*68 = 2176
    float* tS   = Gs + 2176;                // 16*228 = 3648
    float* sh0  = tS + 3648;                // 288
    float* sh1  = sh0 + 288;                // 288
    int*   dst0 = (int*)(sh1 + 288);        // 32
    int*   dst1 = dst0 + 32;                // 32
    float* pbuf = (float*)(dst1 + 32);      // 128

    // -------- one-time loads (all 512 threads): M, W1, constants --------
    for (int i = tid; i < 32 * 112; i += THREADS) {
        int row = i / 112, c4 = i - row * 112;
        cp_async16(&Ms[row * (MSTR2 * 2) + c4 * 4], &g_M[row * 448 + c4 * 4]);
    }
    for (int i = tid; i < 32 * 32; i += THREADS) {
        int row = i >> 5, c4 = i & 31;
        cp_async16(&W1s[row * (W1STR2 * 2) + c4 * 4], &g_W1[row * 128 + c4 * 4]);
    }
    if (tid < 64) { b1s[tid] = rad_b1[tid]; gms[tid] = rad_gamma[tid]; bts[tid] = rad_beta[tid]; }
    if (tid >= 64 && tid < 64 + 256) cS[tid - 64] = g_c[tid - 64];
    if (tid >= 320 && tid < 448) b0s[tid - 320] = proj_b0[tid - 320] * 0.25f;

    // -------- per-group tile prefetch (32 edges) --------
    auto prefetch = [&](int e0, float* shB, int* dstB) {
        if (e0 + 32 <= E) {   // full tile: no bounds math
            const float* xg = edge_scalars + (size_t)e0 * 64;
            #pragma unroll
            for (int r = 0; r < 4; r++) {
                int i = gt + r * 128;            // 0..511
                int e = i >> 4, c4 = i & 15;
                cp_async16(&Xs[e * XSTR + c4 * 4], xg + e * 64 + c4 * 4);
            }
            if (gt < 72)
                cp_async16(&shB[gt * 4], edge_attr + (size_t)e0 * 9 + gt * 4);
            if (gt < 8)
                cp_async16(&dstB[gt * 4], edge_dst + e0 + gt * 4);
        } else {
            #pragma unroll
            for (int r = 0; r < 4; r++) {
                int i = gt + r * 128;
                int e = i >> 4, c4 = i & 15;
                int ge = e0 + e;
                int gc = (ge < E) ? ge : (E - 1);
                cp_async16_zfill(&Xs[e * XSTR + c4 * 4],
                                 edge_scalars + (size_t)gc * 64 + c4 * 4,
                                 (ge < E) ? 16 : 0);
            }
            if (gt < 72) {
                long rem = (long)E * 9 - (long)e0 * 9 - (long)gt * 4;
                int sz = (rem >= 4) ? 16 : ((rem > 0) ? (int)(rem * 4) : 0);
                cp_async16_zfill(&shB[gt * 4], edge_attr + (size_t)e0 * 9 + gt * 4, sz);
            }
            if (gt < 8) {
                int off = gt * 4;
                int ge = e0 + off;
                int gc = (ge + 3 < E) ? ge : ((E >= 4) ? E - 4 : 0);
                int rem = E - ge;
                int sz = (rem >= 4) ? 16 : ((rem > 0) ? rem * 4 : 0);
                cp_async16_zfill(&dstB[off], edge_dst + gc, sz);
            }
        }
    };

    const int stride = gridDim.x * 4;
    int t0 = blockIdx.x * 4 + g;
    if (t0 < nTiles) prefetch(t0 * 32, sh0, dst0);
    asm volatile("cp.async.commit_group;" ::: "memory");
    __syncthreads();   // constants visible; groups diverge after this

    int p = 0;
    for (int t = t0; t < nTiles; t += stride) {
        const int e0 = t * 32;
        float* shP  = p ? sh1 : sh0;
        int*   dstP = p ? dst1 : dst0;

        asm volatile("cp.async.wait_group 0;" ::: "memory");
        barg(g);

        // -------- stage A: h[32x64] = X @ W1 (mma tf32), LN fused --------
        {
            const int mt = wg >> 1;          // 0..1
            const int nq = wg & 1;
            const int m0 = mt * 16;
            float d[4][4] = {};
            const int ar0 = (m0 + (l >> 2)) * XSTR + (l & 3);
            const int ar1 = ar0 + 8 * XSTR;
            const float2* W2 = (const float2*)W1s;
            const int wcol = nq * 32 + (l >> 2);   // float2 col base

            #pragma unroll
            for (int k0 = 0; k0 < 64; k0 += 8) {
                uint32_t a[4];
                a[0] = f2tf32(Xs[ar0 + k0]);
                a[1] = f2tf32(Xs[ar1 + k0]);
                a[2] = f2tf32(Xs[ar0 + k0 + 4]);
                a[3] = f2tf32(Xs[ar1 + k0 + 4]);
                const int wrow = ((k0 >> 3) * 4 + (l & 3)) * W1STR2 + wcol;
                #pragma unroll
                for (int nt = 0; nt < 4; nt++) {
                    float2 bb = W2[wrow + nt * 8];
                    mma_tf32(d[nt], a, __float_as_uint(bb.x), __float_as_uint(bb.y));
                }
            }

            // bias + per-row partial sums over this warp's 32 cols
            float ps0 = 0.f, pq0 = 0.f, ps1 = 0.f, pq1 = 0.f;
            #pragma unroll
            for (int nt = 0; nt < 4; nt++) {
                int c = nq * 32 + nt * 8 + (l & 3) * 2;
                float b0 = b1s[c], b1 = b1s[c + 1];
                d[nt][0] += b0; d[nt][1] += b1;
                d[nt][2] += b0; d[nt][3] += b1;
                ps0 += d[nt][0] + d[nt][1];
                pq0 += d[nt][0] * d[nt][0] + d[nt][1] * d[nt][1];
                ps1 += d[nt][2] + d[nt][3];
                pq1 += d[nt][2] * d[nt][2] + d[nt][3] * d[nt][3];
            }
            #pragma unroll
            for (int o = 1; o <= 2; o <<= 1) {
                ps0 += __shfl_xor_sync(0xffffffffu, ps0, o);
                pq0 += __shfl_xor_sync(0xffffffffu, pq0, o);
                ps1 += __shfl_xor_sync(0xffffffffu, ps1, o);
                pq1 += __shfl_xor_sync(0xffffffffu, pq1, o);
            }
            if ((l & 3) == 0)
                *(float4*)&pbuf[(wg * 8 + (l >> 2)) * 4] = make_float4(ps0, pq0, ps1, pq1);
            barg(g);   // partials visible; ALL stage-A Xs reads done

            // prefetch next tile (Xs now free)
            {
                int tn = t + stride;
                if (tn < nTiles) prefetch(tn * 32, p ? sh0 : sh1, p ? dst0 : dst1);
                asm volatile("cp.async.commit_group;" ::: "memory");
            }

            // merge partner warp's partials -> full 64-col row stats
            float4 pp = *(const float4*)&pbuf[((wg ^ 1) * 8 + (l >> 2)) * 4];
            ps0 += pp.x; pq0 += pp.y; ps1 += pp.z; pq1 += pp.w;
            float mu0   = ps0 * (1.f / 64.f);
            float rstd0 = rsqrtf(pq0 * (1.f / 64.f) - mu0 * mu0 + 1e-5f);
            float mu1   = ps1 * (1.f / 64.f);
            float rstd1 = rsqrtf(pq1 * (1.f / 64.f) - mu1 * mu1 + 1e-5f);

            // normalize + silu + tf32, store G
            const int r0 = m0 + (l >> 2);
            #pragma unroll
            for (int nt = 0; nt < 4; nt++) {
                int c = nq * 32 + nt * 8 + (l & 3) * 2;
                float g0 = gms[c], g1 = gms[c + 1];
                float q0 = bts[c], q1 = bts[c + 1];
                float v00 = (d[nt][0] - mu0) * rstd0 * g0 + q0;
                float v01 = (d[nt][1] - mu0) * rstd0 * g1 + q1;
                float v10 = (d[nt][2] - mu1) * rstd1 * g0 + q0;
                float v11 = (d[nt][3] - mu1) * rstd1 * g1 + q1;
                v00 = __fdividef(v00, 1.f + __expf(-v00));
                v01 = __fdividef(v01, 1.f + __expf(-v01));
                v10 = __fdividef(v10, 1.f + __expf(-v10));
                v11 = __fdividef(v11, 1.f + __expf(-v11));
                *(uint2*)&Gs[r0 * GSTR + c]       = make_uint2(f2tf32(v00), f2tf32(v01));
                *(uint2*)&Gs[(r0 + 8) * GSTR + c] = make_uint2(f2tf32(v10), f2tf32(v11));
            }
        }
        barg(g);   // G visible to group

        // -------- stage B: t[32x224] = G @ M + c (mma tf32) --------
        // each warp: all 32 rows x 56 cols (n0 = wg*56)
        float d[2][7][4] = {};
        const int n0 = wg * 56;
        {
            const uint32_t* Gu = (const uint32_t*)Gs;
            const float2* M2 = (const float2*)Ms;
            const int ar00 = (l >> 2) * GSTR + (l & 3);
            const int bcol = n0 + (l >> 2);

            #pragma unroll
            for (int k0 = 0; k0 < 64; k0 += 8) {
                uint32_t a[2][4];
                #pragma unroll
                for (int mt = 0; mt < 2; mt++) {
                    int base = ar00 + mt * 16 * GSTR + k0;
                    a[mt][0] = Gu[base];
                    a[mt][1] = Gu[base + 8 * GSTR];
                    a[mt][2] = Gu[base + 4];
                    a[mt][3] = Gu[base + 8 * GSTR + 4];
                }
                const int brow = ((k0 >> 3) * 4 + (l & 3)) * MSTR2 + bcol;
                #pragma unroll
                for (int jt = 0; jt < 7; jt++) {
                    float2 bb = M2[brow + jt * 8];
                    uint32_t b0 = __float_as_uint(bb.x);
                    uint32_t b1 = __float_as_uint(bb.y);
                    mma_tf32(d[0][jt], a[0], b0, b1);
                    mma_tf32(d[1][jt], a[1], b0, b1);
                }
            }
        }

        // -------- stage C: two halves of 16 edges --------
        // tS store helper (all 4 warps stage their 56-col slice)
        auto store_half = [&](int half) {
            #pragma unroll
            for (int jt = 0; jt < 7; jt++) {
                int c = n0 + jt * 8 + (l & 3) * 2;
                float c0 = cS[c], c1 = cS[c + 1];
                int r0 = (l >> 2);
                *(float2*)&tS[r0 * TSTR + c] =
                    make_float2(d[half][jt][0] + c0, d[half][jt][1] + c1);
                *(float2*)&tS[(r0 + 8) * TSTR + c] =
                    make_float2(d[half][jt][2] + c0, d[half][jt][3] + c1);
            }
        };

        const float4 b0v = *(const float4*)&b0s[l * 4];
        const bool full = (e0 + 32 <= E);

        // half 0: no leading barg needed (prev tS reads separated by >=3 bargs)
        store_half(0);
        barg(g);
        if (full) {
            #pragma unroll 1
            for (int i = 0; i < 4; i++) {
                const int er = wg * 4 + i;
                scatter_edge<true>(&tS[er * TSTR], &shP[er * 9],
                                   out + (size_t)dstP[er] * 480, b0v, l);
            }
        } else {
            #pragma unroll 1
            for (int i = 0; i < 4; i++) {
                const int er = wg * 4 + i;
                if (e0 + er >= E) continue;
                scatter_edge<false>(&tS[er * TSTR], &shP[er * 9],
                                    out + (size_t)dstP[er] * 480, b0v, l);
            }
        }
        barg(g);   // scatter-half0 tS reads done
        store_half(1);
        barg(g);
        if (full) {
            #pragma unroll 1
            for (int i = 0; i < 4; i++) {
                const int er = wg * 4 + i;
                const int e  = 16 + er;
                scatter_edge<true>(&tS[er * TSTR], &shP[e * 9],
                                   out + (size_t)dstP[e] * 480, b0v, l);
            }
        } else {
            #pragma unroll 1
            for (int i = 0; i < 4; i++) {
                const int er = wg * 4 + i;
                const int e  = 16 + er;
                if (e0 + e >= E) continue;
                scatter_edge<false>(&tS[er * TSTR], &shP[e * 9],
                                    out + (size_t)dstP[e] * 480, b0v, l);
            }
        }
        p ^= 1;
    }
}

// ---------------------------------------------------------------------------
extern "C" void kernel_launch(void* const* d_in, const int* in_sizes, int n_in,
                              void* d_out, int out_size) {
    const float* edge_attr    = (const float*)d_in[1];
    const float* edge_scalars = (const float*)d_in[2];
    const int*   edge_dst     = (const int*)d_in[4];
    const float* exp_w   = (const float*)d_in[6];
    const float* exp_b   = (const float*)d_in[7];
    const float* rad_w1  = (const float*)d_in[8];
    const float* rad_b1  = (const float*)d_in[9];
    const float* rad_gamma = (const float*)d_in[10];
    const float* rad_beta  = (const float*)d_in[11];
    const float* rad_w2  = (const float*)d_in[12];
    const float* rad_b2  = (const float*)d_in[13];
    const float* proj_w0 = (const float*)d_in[14];
    const float* proj_b0 = (const float*)d_in[15];
    const float* proj_w1 = (const float*)d_in[16];
    const float* proj_w2 = (const float*)d_in[17];
    float* out = (float*)d_out;
    const int E = in_sizes[4];

    cudaMemsetAsync(d_out, 0, (size_t)out_size * sizeof(float));

    precompute_kernel<<<69, 1024>>>(exp_w, exp_b, rad_w2, rad_b2,
                                    proj_w0, proj_w1, proj_w2, rad_w1);

    const size_t SMEM_FLOATS = CONST_OFF + 64 * 3 + 256 + 128;   // 54592
    const size_t SMEM_BYTES = SMEM_FLOATS * sizeof(float);        // 218368
    cudaFuncSetAttribute(edge_main_kernel,
                         cudaFuncAttributeMaxDynamicSharedMemorySize, (int)SMEM_BYTES);

    int sms = 148;
    cudaDeviceGetAttribute(&sms, cudaDevAttrMultiProcessorCount, 0);
    const int nTiles = (E + 31) / 32;
    int grid = (nTiles + 3) / 4;
    if (grid > sms) grid = sms;

    edge_main_kernel<<<grid, THREADS, SMEM_BYTES>>>(
        edge_attr, edge_scalars, edge_dst,
        rad_b1, rad_gamma, rad_beta,
        proj_b0, out, E, nTiles);
}

// round 14
// speedup vs baseline: 1.0598x; 1.0598x over previous
#include <cuda_runtime.h>
#include <cuda_bf16.h>
#include <cstdint>

#define THREADS 512
#define RCOLS   224
#define MSTR2   228     // Ms row stride in float2 (mod 16 == 4 -> conflict-free LDS.64)
#define XSTR    68      // Xs row stride (mod 32 == 4 -> conflict-free A frags)
#define GSTR    68
#define W1STR2  68      // W1 row stride in float2 (mod 16 == 4)
#define TSTR    228     // t staging row stride (16 rows per half)

#define ZBLOCKS 256     // zeroing blocks appended to precompute launch

// group-local smem block sizes (floats)
#define GRP_FLOATS (2176 + 2176 + 3648 + 2*288 + 2*32 + 128)   // 8768
#define MS_FLOATS  (32 * MSTR2 * 2)                             // 14592
#define W1_FLOATS  (32 * W1STR2 * 2)                            // 4352
#define CONST_OFF  (MS_FLOATS + W1_FLOATS + 4 * GRP_FLOATS)     // 54016

// Precomputed fused weight M, row-pair packed:
//   g_M[(prow*224 + col)*2 + slot],  prow=(k>>3)*4+(k&3), slot=(k>>2)&1
// bias row c[256] (fp32), W1 packed the same way (64 cols).
__device__ __align__(16) float g_M[32 * 224 * 2];
__device__ __align__(16) float g_c[256];
__device__ __align__(16) float g_W1[32 * 64 * 2];

__device__ __forceinline__ uint32_t f2tf32(float f) {
    uint32_t u;
    asm("cvt.rna.tf32.f32 %0, %1;" : "=r"(u) : "f"(f));
    return u;
}

// ---------------------------------------------------------------------------
// Precompute + output zeroing in ONE launch.
// Blocks 0..64: M rows (64 = bias row). Blocks 65..68: W1 tf32 conversion.
// Blocks 69..69+ZBLOCKS-1: zero d_out (grid-strided float4).
// ---------------------------------------------------------------------------
__global__ __launch_bounds__(1024)
void precompute_kernel(const float* __restrict__ exp_w,
                       const float* __restrict__ exp_b,
                       const float* __restrict__ rad_w2,
                       const float* __restrict__ rad_b2,
                       const float* __restrict__ pw0,
                       const float* __restrict__ pw1,
                       const float* __restrict__ pw2,
                       const float* __restrict__ rad_w1,
                       float* __restrict__ out, int out_size) {
    int k = blockIdx.x;
    int tid = threadIdx.x;

    if (k >= 69) {                       // output zeroing
        int zb = k - 69;
        float4* o4 = (float4*)out;
        int n4 = out_size >> 2;
        const float4 z = make_float4(0.f, 0.f, 0.f, 0.f);
        for (int i = zb * 1024 + tid; i < n4; i += ZBLOCKS * 1024)
            o4[i] = z;
        if (zb == 0 && tid < (out_size & 3))
            out[n4 * 4 + tid] = 0.f;
        return;
    }

    if (k >= 65) {                       // W1 conversion: 4 blocks x 1024
        int i = (k - 65) * 1024 + tid;
        if (i < 64 * 64) {
            int kk = i >> 6, col = i & 63;
            int prow = (kk >> 3) * 4 + (kk & 3);
            int slot = (kk >> 2) & 1;
            g_W1[prow * 128 + col * 2 + slot] = __uint_as_float(f2tf32(rad_w1[i]));
        }
        return;
    }

    __shared__ float s_s[128];
    __shared__ float s_w[384];
    __shared__ float part[4][256];

    if (tid < 128) s_s[tid] = exp_w[tid] + exp_b[tid];
    if (tid >= 128 && tid < 512) {
        int i = tid - 128;
        s_w[i] = (k < 64) ? rad_w2[k * 384 + i] : rad_b2[i];
    }
    __syncthreads();

    const int cs  = tid >> 8;    // 0..3: c chunk
    const int col = tid & 255;   // 0..255
    float acc = 0.f;
    if (col < RCOLS) {
        const float* P;
        int d, woff, pstride;
        if (col < 128)      { P = pw0; d = col;       woff = 0;   pstride = 128; }
        else if (col < 192) { P = pw1; d = col - 128; woff = 128; pstride = 64;  }
        else                { P = pw2; d = col - 192; woff = 256; pstride = 32;  }
        const int c0 = cs * 32;
        #pragma unroll 8
        for (int c = c0; c < c0 + 32; c++)
            acc += s_w[woff + c] * s_s[c] * __ldg(&P[c * pstride + d]);
    }
    part[cs][col] = acc;
    __syncthreads();

    if (tid < 256) {
        float sum = (part[0][tid] + part[1][tid]) + (part[2][tid] + part[3][tid]);
        sum *= 0.25f;   // 1/sqrt(AVG_AGG)
        if (k < 64) {
            if (tid < RCOLS) {
                int prow = (k >> 3) * 4 + (k & 3);
                int slot = (k >> 2) & 1;
                g_M[(prow * 224 + tid) * 2 + slot] = __uint_as_float(f2tf32(sum));
            }
        } else {
            g_c[tid] = sum;
        }
    }
}

// ---------------------------------------------------------------------------
__device__ __forceinline__ void red4(float* p, float a, float b, float c, float d) {
    asm volatile("red.global.add.v4.f32 [%0], {%1, %2, %3, %4};"
                 :: "l"(p), "f"(a), "f"(b), "f"(c), "f"(d) : "memory");
}

__device__ __forceinline__ void cp_async16(void* smem_ptr, const void* gmem) {
    uint32_t s = (uint32_t)__cvta_generic_to_shared(smem_ptr);
    asm volatile("cp.async.cg.shared.global [%0], [%1], 16;" :: "r"(s), "l"(gmem));
}
__device__ __forceinline__ void cp_async16_zfill(void* smem_ptr, const void* gmem, int srcsz) {
    uint32_t s = (uint32_t)__cvta_generic_to_shared(smem_ptr);
    asm volatile("cp.async.cg.shared.global [%0], [%1], 16, %2;"
                 :: "r"(s), "l"(gmem), "r"(srcsz));
}

__device__ __forceinline__ void mma_tf32(float d[4], const uint32_t a[4],
                                         uint32_t b0, uint32_t b1) {
    asm volatile(
        "mma.sync.aligned.m16n8k8.row.col.f32.tf32.tf32.f32 "
        "{%0,%1,%2,%3}, {%4,%5,%6,%7}, {%8,%9}, {%0,%1,%2,%3};"
        : "+f"(d[0]), "+f"(d[1]), "+f"(d[2]), "+f"(d[3])
        : "r"(a[0]), "r"(a[1]), "r"(a[2]), "r"(a[3]), "r"(b0), "r"(b1));
}

// group barrier (named): 128 threads of group g
__device__ __forceinline__ void barg(int g) {
    asm volatile("bar.sync %0, %1;" :: "r"(g + 1), "r"(128) : "memory");
}

// ---------------------------------------------------------------------------
// Persistent kernel, FOUR independent 128-thread warp-groups per CTA.
// Each group owns a stream of 32-edge tiles; groups overlap GEMM vs scatter.
// (R12 structure, byte-for-byte.)
// ---------------------------------------------------------------------------
__global__ __launch_bounds__(THREADS, 1)
void edge_main_kernel(const float* __restrict__ edge_attr,
                      const float* __restrict__ edge_scalars,
                      const int*   __restrict__ edge_dst,
                      const float* __restrict__ rad_b1,
                      const float* __restrict__ rad_gamma,
                      const float* __restrict__ rad_beta,
                      const float* __restrict__ proj_b0,
                      float* __restrict__ out,
                      int E, int nTiles)
{
    extern __shared__ float smem[];
    float* Ms   = smem;                     // 14592 (32 x 228 float2)
    float* W1s  = Ms + MS_FLOATS;           // 4352  (32 x 68 float2)
    // constants
    float* b1s  = smem + CONST_OFF;         // 64
    float* gms  = b1s + 64;                 // 64
    float* bts  = gms + 64;                 // 64
    float* cS   = bts + 64;                 // 256
    float* b0s  = cS + 256;                 // 128

    const int tid = threadIdx.x;
    const int g   = tid >> 7;        // warp-group 0..3
    const int gt  = tid & 127;       // thread-in-group
    const int l   = tid & 31;
    const int wg  = (tid >> 5) & 3;  // warp-in-group 0..3

    // group-local buffers
    float* GB   = smem + MS_FLOATS + W1_FLOATS + g * GRP_FLOATS;
    float* Xs   = GB;                       // 32*68 = 2176
    float* Gs   = Xs + 2176;                // 32*68 = 2176
    float* tS   = Gs + 2176;                // 16*228 = 3648
    float* sh0  = tS + 3648;                // 288
    float* sh1  = sh0 + 288;                // 288
    int*   dst0 = (int*)(sh1 + 288);        // 32
    int*   dst1 = dst0 + 32;                // 32
    float* pbuf = (float*)(dst1 + 32);      // 128

    // -------- one-time loads (all 512 threads): M, W1, constants --------
    for (int i = tid; i < 32 * 112; i += THREADS) {
        int row = i / 112, c4 = i - row * 112;
        cp_async16(&Ms[row * (MSTR2 * 2) + c4 * 4], &g_M[row * 448 + c4 * 4]);
    }
    for (int i = tid; i < 32 * 32; i += THREADS) {
        int row = i >> 5, c4 = i & 31;
        cp_async16(&W1s[row * (W1STR2 * 2) + c4 * 4], &g_W1[row * 128 + c4 * 4]);
    }
    if (tid < 64) { b1s[tid] = rad_b1[tid]; gms[tid] = rad_gamma[tid]; bts[tid] = rad_beta[tid]; }
    if (tid >= 64 && tid < 64 + 256) cS[tid - 64] = g_c[tid - 64];
    if (tid >= 320 && tid < 448) b0s[tid - 320] = proj_b0[tid - 320] * 0.25f;

    // -------- per-group tile prefetch (32 edges) --------
    auto prefetch = [&](int e0, float* shB, int* dstB) {
        if (e0 + 32 <= E) {   // full tile: no bounds math
            const float* xg = edge_scalars + (size_t)e0 * 64;
            #pragma unroll
            for (int r = 0; r < 4; r++) {
                int i = gt + r * 128;            // 0..511
                int e = i >> 4, c4 = i & 15;
                cp_async16(&Xs[e * XSTR + c4 * 4], xg + e * 64 + c4 * 4);
            }
            if (gt < 72)
                cp_async16(&shB[gt * 4], edge_attr + (size_t)e0 * 9 + gt * 4);
            if (gt < 8)
                cp_async16(&dstB[gt * 4], edge_dst + e0 + gt * 4);
        } else {
            #pragma unroll
            for (int r = 0; r < 4; r++) {
                int i = gt + r * 128;
                int e = i >> 4, c4 = i & 15;
                int ge = e0 + e;
                int gc = (ge < E) ? ge : (E - 1);
                cp_async16_zfill(&Xs[e * XSTR + c4 * 4],
                                 edge_scalars + (size_t)gc * 64 + c4 * 4,
                                 (ge < E) ? 16 : 0);
            }
            if (gt < 72) {
                long rem = (long)E * 9 - (long)e0 * 9 - (long)gt * 4;
                int sz = (rem >= 4) ? 16 : ((rem > 0) ? (int)(rem * 4) : 0);
                cp_async16_zfill(&shB[gt * 4], edge_attr + (size_t)e0 * 9 + gt * 4, sz);
            }
            if (gt < 8) {
                int off = gt * 4;
                int ge = e0 + off;
                int gc = (ge + 3 < E) ? ge : ((E >= 4) ? E - 4 : 0);
                int rem = E - ge;
                int sz = (rem >= 4) ? 16 : ((rem > 0) ? rem * 4 : 0);
                cp_async16_zfill(&dstB[off], edge_dst + gc, sz);
            }
        }
    };

    const int stride = gridDim.x * 4;
    int t0 = blockIdx.x * 4 + g;
    if (t0 < nTiles) prefetch(t0 * 32, sh0, dst0);
    asm volatile("cp.async.commit_group;" ::: "memory");
    __syncthreads();   // constants visible; groups diverge after this

    int p = 0;
    for (int t = t0; t < nTiles; t += stride) {
        const int e0 = t * 32;
        float* shP  = p ? sh1 : sh0;
        int*   dstP = p ? dst1 : dst0;

        asm volatile("cp.async.wait_group 0;" ::: "memory");
        barg(g);

        // -------- stage A: h[32x64] = X @ W1 (mma tf32), LN fused --------
        {
            const int mt = wg >> 1;          // 0..1
            const int nq = wg & 1;
            const int m0 = mt * 16;
            float d[4][4] = {};
            const int ar0 = (m0 + (l >> 2)) * XSTR + (l & 3);
            const int ar1 = ar0 + 8 * XSTR;
            const float2* W2 = (const float2*)W1s;
            const int wcol = nq * 32 + (l >> 2);   // float2 col base

            #pragma unroll
            for (int k0 = 0; k0 < 64; k0 += 8) {
                uint32_t a[4];
                a[0] = f2tf32(Xs[ar0 + k0]);
                a[1] = f2tf32(Xs[ar1 + k0]);
                a[2] = f2tf32(Xs[ar0 + k0 + 4]);
                a[3] = f2tf32(Xs[ar1 + k0 + 4]);
                const int wrow = ((k0 >> 3) * 4 + (l & 3)) * W1STR2 + wcol;
                #pragma unroll
                for (int nt = 0; nt < 4; nt++) {
                    float2 bb = W2[wrow + nt * 8];
                    mma_tf32(d[nt], a, __float_as_uint(bb.x), __float_as_uint(bb.y));
                }
            }

            // bias + per-row partial sums over this warp's 32 cols
            float ps0 = 0.f, pq0 = 0.f, ps1 = 0.f, pq1 = 0.f;
            #pragma unroll
            for (int nt = 0; nt < 4; nt++) {
                int c = nq * 32 + nt * 8 + (l & 3) * 2;
                float b0 = b1s[c], b1 = b1s[c + 1];
                d[nt][0] += b0; d[nt][1] += b1;
                d[nt][2] += b0; d[nt][3] += b1;
                ps0 += d[nt][0] + d[nt][1];
                pq0 += d[nt][0] * d[nt][0] + d[nt][1] * d[nt][1];
                ps1 += d[nt][2] + d[nt][3];
                pq1 += d[nt][2] * d[nt][2] + d[nt][3] * d[nt][3];
            }
            #pragma unroll
            for (int o = 1; o <= 2; o <<= 1) {
                ps0 += __shfl_xor_sync(0xffffffffu, ps0, o);
                pq0 += __shfl_xor_sync(0xffffffffu, pq0, o);
                ps1 += __shfl_xor_sync(0xffffffffu, ps1, o);
                pq1 += __shfl_xor_sync(0xffffffffu, pq1, o);
            }
            if ((l & 3) == 0)
                *(float4*)&pbuf[(wg * 8 + (l >> 2)) * 4] = make_float4(ps0, pq0, ps1, pq1);
            barg(g);   // partials visible; ALL stage-A Xs reads done

            // prefetch next tile (Xs now free)
            {
                int tn = t + stride;
                if (tn < nTiles) prefetch(tn * 32, p ? sh0 : sh1, p ? dst0 : dst1);
                asm volatile("cp.async.commit_group;" ::: "memory");
            }

            // merge partner warp's partials -> full 64-col row stats
            float4 pp = *(const float4*)&pbuf[((wg ^ 1) * 8 + (l >> 2)) * 4];
            ps0 += pp.x; pq0 += pp.y; ps1 += pp.z; pq1 += pp.w;
            float mu0   = ps0 * (1.f / 64.f);
            float rstd0 = rsqrtf(pq0 * (1.f / 64.f) - mu0 * mu0 + 1e-5f);
            float mu1   = ps1 * (1.f / 64.f);
            float rstd1 = rsqrtf(pq1 * (1.f / 64.f) - mu1 * mu1 + 1e-5f);

            // normalize + silu + tf32, store G
            const int r0 = m0 + (l >> 2);
            #pragma unroll
            for (int nt = 0; nt < 4; nt++) {
                int c = nq * 32 + nt * 8 + (l & 3) * 2;
                float g0 = gms[c], g1 = gms[c + 1];
                float q0 = bts[c], q1 = bts[c + 1];
                float v00 = (d[nt][0] - mu0) * rstd0 * g0 + q0;
                float v01 = (d[nt][1] - mu0) * rstd0 * g1 + q1;
                float v10 = (d[nt][2] - mu1) * rstd1 * g0 + q0;
                float v11 = (d[nt][3] - mu1) * rstd1 * g1 + q1;
                v00 = __fdividef(v00, 1.f + __expf(-v00));
                v01 = __fdividef(v01, 1.f + __expf(-v01));
                v10 = __fdividef(v10, 1.f + __expf(-v10));
                v11 = __fdividef(v11, 1.f + __expf(-v11));
                *(uint2*)&Gs[r0 * GSTR + c]       = make_uint2(f2tf32(v00), f2tf32(v01));
                *(uint2*)&Gs[(r0 + 8) * GSTR + c] = make_uint2(f2tf32(v10), f2tf32(v11));
            }
        }
        barg(g);   // G visible to group

        // -------- stage B: t[32x224] = G @ M + c (mma tf32) --------
        // each warp: all 32 rows x 56 cols (n0 = wg*56)
        float d[2][7][4] = {};
        const int n0 = wg * 56;
        {
            const uint32_t* Gu = (const uint32_t*)Gs;
            const float2* M2 = (const float2*)Ms;
            const int ar00 = (l >> 2) * GSTR + (l & 3);
            const int bcol = n0 + (l >> 2);

            #pragma unroll
            for (int k0 = 0; k0 < 64; k0 += 8) {
                uint32_t a[2][4];
                #pragma unroll
                for (int mt = 0; mt < 2; mt++) {
                    int base = ar00 + mt * 16 * GSTR + k0;
                    a[mt][0] = Gu[base];
                    a[mt][1] = Gu[base + 8 * GSTR];
                    a[mt][2] = Gu[base + 4];
                    a[mt][3] = Gu[base + 8 * GSTR + 4];
                }
                const int brow = ((k0 >> 3) * 4 + (l & 3)) * MSTR2 + bcol;
                #pragma unroll
                for (int jt = 0; jt < 7; jt++) {
                    float2 bb = M2[brow + jt * 8];
                    uint32_t b0 = __float_as_uint(bb.x);
                    uint32_t b1 = __float_as_uint(bb.y);
                    mma_tf32(d[0][jt], a[0], b0, b1);
                    mma_tf32(d[1][jt], a[1], b0, b1);
                }
            }
        }

        // -------- stage C: two halves of 16 edges --------
        #pragma unroll
        for (int half = 0; half < 2; half++) {
            barg(g);   // prev tS reads done / stage-B Gs reads done
            {
                // all 4 warps stage their 56-col slice of this half's 16 rows
                #pragma unroll
                for (int jt = 0; jt < 7; jt++) {
                    int c = n0 + jt * 8 + (l & 3) * 2;
                    float c0 = cS[c], c1 = cS[c + 1];
                    int r0 = (l >> 2);
                    *(float2*)&tS[r0 * TSTR + c] =
                        make_float2(d[half][jt][0] + c0, d[half][jt][1] + c1);
                    *(float2*)&tS[(r0 + 8) * TSTR + c] =
                        make_float2(d[half][jt][2] + c0, d[half][jt][3] + c1);
                }
            }
            barg(g);

            // balanced coalesced scatter: 4 warps x 4 edges
            const float4 b0v = *(const float4*)&b0s[l * 4];
            #pragma unroll 1
            for (int i = 0; i < 4; i++) {
                const int er = wg * 4 + i;            // row in tS (0..15)
                const int e  = half * 16 + er;        // edge in tile
                if (e0 + e >= E) continue;
                const float* te = &tS[er * TSTR];
                const float* sh = &shP[e * 9];
                float* base = out + (size_t)dstP[e] * 480;
                const float s0 = sh[0];

                // region 0: cols 0..127, one red4 per lane
                {
                    float4 v = *(const float4*)&te[l * 4];
                    red4(base + l * 4,
                         fmaf(s0, v.x, b0v.x), fmaf(s0, v.y, b0v.y),
                         fmaf(s0, v.z, b0v.z), fmaf(s0, v.w, b0v.w));
                }
                // regions 1+2 merged: 88 quad-items in 3 rounds
                #pragma unroll
                for (int r = 0; r < 3; r++) {
                    int j = l + r * 32;
                    if (j < 88) {
                        int  r2   = (j >= 48);
                        int  jj   = r2 ? (j - 48) : j;
                        int  pidx = 4 * jj;
                        int  q    = r2 ? ((pidx * 0x3334) >> 16)
                                       : ((pidx * 0x5556) >> 16);
                        int  mod  = r2 ? 5 : 3;
                        int  m    = pidx - mod * q;
                        const float* tb_ = te + (r2 ? 192 : 128);
                        int  qb   = q + 1;
                        if (r2 && qb > 31) qb = 31;
                        float ta  = tb_[q];
                        float tbv = tb_[qb];
                        const float* shb = sh + (r2 ? 4 : 1);
                        float v[4];
                        #pragma unroll
                        for (int ii = 0; ii < 4; ii++) {
                            int mi = m + ii;
                            int f  = (mi >= mod);
                            float sv = shb[mi - mod * f];
                            v[ii] = (f ? tbv : ta) * sv;
                        }
                        red4(base + (r2 ? 320 : 128) + pidx, v[0], v[1], v[2], v[3]);
                    }
                }
            }
        }
        p ^= 1;
    }
}

// ---------------------------------------------------------------------------
extern "C" void kernel_launch(void* const* d_in, const int* in_sizes, int n_in,
                              void* d_out, int out_size) {
    const float* edge_attr    = (const float*)d_in[1];
    const float* edge_scalars = (const float*)d_in[2];
    const int*   edge_dst     = (const int*)d_in[4];
    const float* exp_w   = (const float*)d_in[6];
    const float* exp_b   = (const float*)d_in[7];
    const float* rad_w1  = (const float*)d_in[8];
    const float* rad_b1  = (const float*)d_in[9];
    const float* rad_gamma = (const float*)d_in[10];
    const float* rad_beta  = (const float*)d_in[11];
    const float* rad_w2  = (const float*)d_in[12];
    const float* rad_b2  = (const float*)d_in[13];
    const float* proj_w0 = (const float*)d_in[14];
    const float* proj_b0 = (const float*)d_in[15];
    const float* proj_w1 = (const float*)d_in[16];
    const float* proj_w2 = (const float*)d_in[17];
    float* out = (float*)d_out;
    const int E = in_sizes[4];

    // precompute + output zeroing fused (no separate memset)
    precompute_kernel<<<69 + ZBLOCKS, 1024>>>(exp_w, exp_b, rad_w2, rad_b2,
                                              proj_w0, proj_w1, proj_w2, rad_w1,
                                              out, out_size);

    const size_t SMEM_FLOATS = CONST_OFF + 64 * 3 + 256 + 128;   // 54592
    const size_t SMEM_BYTES = SMEM_FLOATS * sizeof(float);        // 218368
    cudaFuncSetAttribute(edge_main_kernel,
                         cudaFuncAttributeMaxDynamicSharedMemorySize, (int)SMEM_BYTES);

    int sms = 148;
    cudaDeviceGetAttribute(&sms, cudaDevAttrMultiProcessorCount, 0);
    const int nTiles = (E + 31) / 32;
    int grid = (nTiles + 3) / 4;
    if (grid > sms) grid = sms;

    edge_main_kernel<<<grid, THREADS, SMEM_BYTES>>>(
        edge_attr, edge_scalars, edge_dst,
        rad_b1, rad_gamma, rad_beta,
        proj_b0, out, E, nTiles);
}

// round 15
// speedup vs baseline: 1.0760x; 1.0152x over previous
#include <cuda_runtime.h>
#include <cuda_bf16.h>
#include <cstdint>

#define THREADS 512
#define RCOLS   224
#define MSTR2   228     // Ms row stride in float2 (mod 16 == 4 -> conflict-free LDS.64)
#define XSTR    68      // Xs row stride (mod 32 == 4 -> conflict-free A frags)
#define GSTR    68
#define W1STR2  68      // W1 row stride in float2 (mod 16 == 4)
#define TSTR    228     // t staging row stride (16 rows per half)

#define ZBLOCKS 256     // zeroing blocks appended to precompute launch

// group-local smem block sizes (floats)
#define GRP_FLOATS (2176 + 2176 + 3648 + 2*288 + 2*32 + 128 + 4)  // 8772
#define MS_FLOATS  (32 * MSTR2 * 2)                                // 14592
#define W1_FLOATS  (32 * W1STR2 * 2)                               // 4352
#define CONST_OFF  (MS_FLOATS + W1_FLOATS + 4 * GRP_FLOATS)        // 54032

// Precomputed fused weight M, row-pair packed:
//   g_M[(prow*224 + col)*2 + slot],  prow=(k>>3)*4+(k&3), slot=(k>>2)&1
// bias row c[256] (fp32), W1 packed the same way (64 cols).
__device__ __align__(16) float g_M[32 * 224 * 2];
__device__ __align__(16) float g_c[256];
__device__ __align__(16) float g_W1[32 * 64 * 2];
__device__ int g_tile_ctr;                 // work-stealing cursor

__device__ __forceinline__ uint32_t f2tf32(float f) {
    uint32_t u;
    asm("cvt.rna.tf32.f32 %0, %1;" : "=r"(u) : "f"(f));
    return u;
}

// ---------------------------------------------------------------------------
// Precompute + output zeroing in ONE launch.
// Blocks 0..64: M rows (64 = bias row). Blocks 65..68: W1 tf32 conversion.
// Blocks 69..69+ZBLOCKS-1: zero d_out (grid-strided float4).
// Block 0 thread 0 also resets the work-stealing counter.
// ---------------------------------------------------------------------------
__global__ __launch_bounds__(1024)
void precompute_kernel(const float* __restrict__ exp_w,
                       const float* __restrict__ exp_b,
                       const float* __restrict__ rad_w2,
                       const float* __restrict__ rad_b2,
                       const float* __restrict__ pw0,
                       const float* __restrict__ pw1,
                       const float* __restrict__ pw2,
                       const float* __restrict__ rad_w1,
                       float* __restrict__ out, int out_size,
                       int ctr_init) {
    int k = blockIdx.x;
    int tid = threadIdx.x;

    if (k == 0 && tid == 0) g_tile_ctr = ctr_init;

    if (k >= 69) {                       // output zeroing
        int zb = k - 69;
        float4* o4 = (float4*)out;
        int n4 = out_size >> 2;
        const float4 z = make_float4(0.f, 0.f, 0.f, 0.f);
        for (int i = zb * 1024 + tid; i < n4; i += ZBLOCKS * 1024)
            o4[i] = z;
        if (zb == 0 && tid < (out_size & 3))
            out[n4 * 4 + tid] = 0.f;
        return;
    }

    if (k >= 65) {                       // W1 conversion: 4 blocks x 1024
        int i = (k - 65) * 1024 + tid;
        if (i < 64 * 64) {
            int kk = i >> 6, col = i & 63;
            int prow = (kk >> 3) * 4 + (kk & 3);
            int slot = (kk >> 2) & 1;
            g_W1[prow * 128 + col * 2 + slot] = __uint_as_float(f2tf32(rad_w1[i]));
        }
        return;
    }

    __shared__ float s_s[128];
    __shared__ float s_w[384];
    __shared__ float part[4][256];

    if (tid < 128) s_s[tid] = exp_w[tid] + exp_b[tid];
    if (tid >= 128 && tid < 512) {
        int i = tid - 128;
        s_w[i] = (k < 64) ? rad_w2[k * 384 + i] : rad_b2[i];
    }
    __syncthreads();

    const int cs  = tid >> 8;    // 0..3: c chunk
    const int col = tid & 255;   // 0..255
    float acc = 0.f;
    if (col < RCOLS) {
        const float* P;
        int d, woff, pstride;
        if (col < 128)      { P = pw0; d = col;       woff = 0;   pstride = 128; }
        else if (col < 192) { P = pw1; d = col - 128; woff = 128; pstride = 64;  }
        else                { P = pw2; d = col - 192; woff = 256; pstride = 32;  }
        const int c0 = cs * 32;
        #pragma unroll 8
        for (int c = c0; c < c0 + 32; c++)
            acc += s_w[woff + c] * s_s[c] * __ldg(&P[c * pstride + d]);
    }
    part[cs][col] = acc;
    __syncthreads();

    if (tid < 256) {
        float sum = (part[0][tid] + part[1][tid]) + (part[2][tid] + part[3][tid]);
        sum *= 0.25f;   // 1/sqrt(AVG_AGG)
        if (k < 64) {
            if (tid < RCOLS) {
                int prow = (k >> 3) * 4 + (k & 3);
                int slot = (k >> 2) & 1;
                g_M[(prow * 224 + tid) * 2 + slot] = __uint_as_float(f2tf32(sum));
            }
        } else {
            g_c[tid] = sum;
        }
    }
}

// ---------------------------------------------------------------------------
__device__ __forceinline__ void red4(float* p, float a, float b, float c, float d) {
    asm volatile("red.global.add.v4.f32 [%0], {%1, %2, %3, %4};"
                 :: "l"(p), "f"(a), "f"(b), "f"(c), "f"(d) : "memory");
}

__device__ __forceinline__ void cp_async16(void* smem_ptr, const void* gmem) {
    uint32_t s = (uint32_t)__cvta_generic_to_shared(smem_ptr);
    asm volatile("cp.async.cg.shared.global [%0], [%1], 16;" :: "r"(s), "l"(gmem));
}
__device__ __forceinline__ void cp_async16_zfill(void* smem_ptr, const void* gmem, int srcsz) {
    uint32_t s = (uint32_t)__cvta_generic_to_shared(smem_ptr);
    asm volatile("cp.async.cg.shared.global [%0], [%1], 16, %2;"
                 :: "r"(s), "l"(gmem), "r"(srcsz));
}

__device__ __forceinline__ void mma_tf32(float d[4], const uint32_t a[4],
                                         uint32_t b0, uint32_t b1) {
    asm volatile(
        "mma.sync.aligned.m16n8k8.row.col.f32.tf32.tf32.f32 "
        "{%0,%1,%2,%3}, {%4,%5,%6,%7}, {%8,%9}, {%0,%1,%2,%3};"
        : "+f"(d[0]), "+f"(d[1]), "+f"(d[2]), "+f"(d[3])
        : "r"(a[0]), "r"(a[1]), "r"(a[2]), "r"(a[3]), "r"(b0), "r"(b1));
}

// group barrier (named): 128 threads of group g
__device__ __forceinline__ void barg(int g) {
    asm volatile("bar.sync %0, %1;" :: "r"(g + 1), "r"(128) : "memory");
}

// ---------------------------------------------------------------------------
// Persistent kernel, FOUR independent 128-thread warp-groups per CTA.
// Each group takes its first 32-edge tile statically, then steals the rest
// from a global cursor (removes static tail imbalance).
// ---------------------------------------------------------------------------
__global__ __launch_bounds__(THREADS, 1)
void edge_main_kernel(const float* __restrict__ edge_attr,
                      const float* __restrict__ edge_scalars,
                      const int*   __restrict__ edge_dst,
                      const float* __restrict__ rad_b1,
                      const float* __restrict__ rad_gamma,
                      const float* __restrict__ rad_beta,
                      const float* __restrict__ proj_b0,
                      float* __restrict__ out,
                      int E, int nTiles)
{
    extern __shared__ float smem[];
    float* Ms   = smem;                     // 14592 (32 x 228 float2)
    float* W1s  = Ms + MS_FLOATS;           // 4352  (32 x 68 float2)
    // constants
    float* b1s  = smem + CONST_OFF;         // 64
    float* gms  = b1s + 64;                 // 64
    float* bts  = gms + 64;                 // 64
    float* cS   = bts + 64;                 // 256
    float* b0s  = cS + 256;                 // 128

    const int tid = threadIdx.x;
    const int g   = tid >> 7;        // warp-group 0..3
    const int gt  = tid & 127;       // thread-in-group
    const int l   = tid & 31;
    const int wg  = (tid >> 5) & 3;  // warp-in-group 0..3

    // group-local buffers
    float* GB   = smem + MS_FLOATS + W1_FLOATS + g * GRP_FLOATS;
    float* Xs   = GB;                       // 32*68 = 2176
    float* Gs   = Xs + 2176;                // 32*68 = 2176
    float* tS   = Gs + 2176;                // 16*228 = 3648
    float* sh0  = tS + 3648;                // 288
    float* sh1  = sh0 + 288;                // 288
    int*   dst0 = (int*)(sh1 + 288);        // 32
    int*   dst1 = dst0 + 32;                // 32
    float* pbuf = (float*)(dst1 + 32);      // 128
    int*   nextS = (int*)(pbuf + 128);      // 1 (+3 pad)

    // -------- one-time loads (all 512 threads): M, W1, constants --------
    for (int i = tid; i < 32 * 112; i += THREADS) {
        int row = i / 112, c4 = i - row * 112;
        cp_async16(&Ms[row * (MSTR2 * 2) + c4 * 4], &g_M[row * 448 + c4 * 4]);
    }
    for (int i = tid; i < 32 * 32; i += THREADS) {
        int row = i >> 5, c4 = i & 31;
        cp_async16(&W1s[row * (W1STR2 * 2) + c4 * 4], &g_W1[row * 128 + c4 * 4]);
    }
    if (tid < 64) { b1s[tid] = rad_b1[tid]; gms[tid] = rad_gamma[tid]; bts[tid] = rad_beta[tid]; }
    if (tid >= 64 && tid < 64 + 256) cS[tid - 64] = g_c[tid - 64];
    if (tid >= 320 && tid < 448) b0s[tid - 320] = proj_b0[tid - 320] * 0.25f;

    // -------- per-group tile prefetch (32 edges) --------
    auto prefetch = [&](int e0, float* shB, int* dstB) {
        if (e0 + 32 <= E) {   // full tile: no bounds math
            const float* xg = edge_scalars + (size_t)e0 * 64;
            #pragma unroll
            for (int r = 0; r < 4; r++) {
                int i = gt + r * 128;            // 0..511
                int e = i >> 4, c4 = i & 15;
                cp_async16(&Xs[e * XSTR + c4 * 4], xg + e * 64 + c4 * 4);
            }
            if (gt < 72)
                cp_async16(&shB[gt * 4], edge_attr + (size_t)e0 * 9 + gt * 4);
            if (gt < 8)
                cp_async16(&dstB[gt * 4], edge_dst + e0 + gt * 4);
        } else {
            #pragma unroll
            for (int r = 0; r < 4; r++) {
                int i = gt + r * 128;
                int e = i >> 4, c4 = i & 15;
                int ge = e0 + e;
                int gc = (ge < E) ? ge : (E - 1);
                cp_async16_zfill(&Xs[e * XSTR + c4 * 4],
                                 edge_scalars + (size_t)gc * 64 + c4 * 4,
                                 (ge < E) ? 16 : 0);
            }
            if (gt < 72) {
                long rem = (long)E * 9 - (long)e0 * 9 - (long)gt * 4;
                int sz = (rem >= 4) ? 16 : ((rem > 0) ? (int)(rem * 4) : 0);
                cp_async16_zfill(&shB[gt * 4], edge_attr + (size_t)e0 * 9 + gt * 4, sz);
            }
            if (gt < 8) {
                int off = gt * 4;
                int ge = e0 + off;
                int gc = (ge + 3 < E) ? ge : ((E >= 4) ? E - 4 : 0);
                int rem = E - ge;
                int sz = (rem >= 4) ? 16 : ((rem > 0) ? rem * 4 : 0);
                cp_async16_zfill(&dstB[off], edge_dst + gc, sz);
            }
        }
    };

    int tCur = blockIdx.x * 4 + g;   // first tile static
    if (tCur < nTiles) prefetch(tCur * 32, sh0, dst0);
    asm volatile("cp.async.commit_group;" ::: "memory");
    __syncthreads();   // constants visible; groups diverge after this

    int p = 0;
    while (tCur < nTiles) {
        const int e0 = tCur * 32;
        float* shP  = p ? sh1 : sh0;
        int*   dstP = p ? dst1 : dst0;

        asm volatile("cp.async.wait_group 0;" ::: "memory");
        barg(g);

        int tNext;
        // -------- stage A: h[32x64] = X @ W1 (mma tf32), LN fused --------
        {
            const int mt = wg >> 1;          // 0..1
            const int nq = wg & 1;
            const int m0 = mt * 16;
            float d[4][4] = {};
            const int ar0 = (m0 + (l >> 2)) * XSTR + (l & 3);
            const int ar1 = ar0 + 8 * XSTR;
            const float2* W2 = (const float2*)W1s;
            const int wcol = nq * 32 + (l >> 2);   // float2 col base

            #pragma unroll
            for (int k0 = 0; k0 < 64; k0 += 8) {
                uint32_t a[4];
                a[0] = f2tf32(Xs[ar0 + k0]);
                a[1] = f2tf32(Xs[ar1 + k0]);
                a[2] = f2tf32(Xs[ar0 + k0 + 4]);
                a[3] = f2tf32(Xs[ar1 + k0 + 4]);
                const int wrow = ((k0 >> 3) * 4 + (l & 3)) * W1STR2 + wcol;
                #pragma unroll
                for (int nt = 0; nt < 4; nt++) {
                    float2 bb = W2[wrow + nt * 8];
                    mma_tf32(d[nt], a, __float_as_uint(bb.x), __float_as_uint(bb.y));
                }
            }

            // bias + per-row partial sums over this warp's 32 cols
            float ps0 = 0.f, pq0 = 0.f, ps1 = 0.f, pq1 = 0.f;
            #pragma unroll
            for (int nt = 0; nt < 4; nt++) {
                int c = nq * 32 + nt * 8 + (l & 3) * 2;
                float b0 = b1s[c], b1 = b1s[c + 1];
                d[nt][0] += b0; d[nt][1] += b1;
                d[nt][2] += b0; d[nt][3] += b1;
                ps0 += d[nt][0] + d[nt][1];
                pq0 += d[nt][0] * d[nt][0] + d[nt][1] * d[nt][1];
                ps1 += d[nt][2] + d[nt][3];
                pq1 += d[nt][2] * d[nt][2] + d[nt][3] * d[nt][3];
            }
            #pragma unroll
            for (int o = 1; o <= 2; o <<= 1) {
                ps0 += __shfl_xor_sync(0xffffffffu, ps0, o);
                pq0 += __shfl_xor_sync(0xffffffffu, pq0, o);
                ps1 += __shfl_xor_sync(0xffffffffu, ps1, o);
                pq1 += __shfl_xor_sync(0xffffffffu, pq1, o);
            }
            if ((l & 3) == 0)
                *(float4*)&pbuf[(wg * 8 + (l >> 2)) * 4] = make_float4(ps0, pq0, ps1, pq1);
            // steal next tile (one thread per group)
            if (gt == 0) nextS[0] = atomicAdd(&g_tile_ctr, 1);
            barg(g);   // partials + nextS visible; ALL stage-A Xs reads done

            // prefetch next tile (Xs now free)
            tNext = nextS[0];
            if (tNext < nTiles) prefetch(tNext * 32, p ? sh0 : sh1, p ? dst0 : dst1);
            asm volatile("cp.async.commit_group;" ::: "memory");

            // merge partner warp's partials -> full 64-col row stats
            float4 pp = *(const float4*)&pbuf[((wg ^ 1) * 8 + (l >> 2)) * 4];
            ps0 += pp.x; pq0 += pp.y; ps1 += pp.z; pq1 += pp.w;
            float mu0   = ps0 * (1.f / 64.f);
            float rstd0 = rsqrtf(pq0 * (1.f / 64.f) - mu0 * mu0 + 1e-5f);
            float mu1   = ps1 * (1.f / 64.f);
            float rstd1 = rsqrtf(pq1 * (1.f / 64.f) - mu1 * mu1 + 1e-5f);

            // normalize + silu + tf32, store G
            const int r0 = m0 + (l >> 2);
            #pragma unroll
            for (int nt = 0; nt < 4; nt++) {
                int c = nq * 32 + nt * 8 + (l & 3) * 2;
                float g0 = gms[c], g1 = gms[c + 1];
                float q0 = bts[c], q1 = bts[c + 1];
                float v00 = (d[nt][0] - mu0) * rstd0 * g0 + q0;
                float v01 = (d[nt][1] - mu0) * rstd0 * g1 + q1;
                float v10 = (d[nt][2] - mu1) * rstd1 * g0 + q0;
                float v11 = (d[nt][3] - mu1) * rstd1 * g1 + q1;
                v00 = __fdividef(v00, 1.f + __expf(-v00));
                v01 = __fdividef(v01, 1.f + __expf(-v01));
                v10 = __fdividef(v10, 1.f + __expf(-v10));
                v11 = __fdividef(v11, 1.f + __expf(-v11));
                *(uint2*)&Gs[r0 * GSTR + c]       = make_uint2(f2tf32(v00), f2tf32(v01));
                *(uint2*)&Gs[(r0 + 8) * GSTR + c] = make_uint2(f2tf32(v10), f2tf32(v11));
            }
        }
        barg(g);   // G visible to group

        // -------- stage B: t[32x224] = G @ M + c (mma tf32) --------
        // each warp: all 32 rows x 56 cols (n0 = wg*56)
        float d[2][7][4] = {};
        const int n0 = wg * 56;
        {
            const uint32_t* Gu = (const uint32_t*)Gs;
            const float2* M2 = (const float2*)Ms;
            const int ar00 = (l >> 2) * GSTR + (l & 3);
            const int bcol = n0 + (l >> 2);

            #pragma unroll
            for (int k0 = 0; k0 < 64; k0 += 8) {
                uint32_t a[2][4];
                #pragma unroll
                for (int mt = 0; mt < 2; mt++) {
                    int base = ar00 + mt * 16 * GSTR + k0;
                    a[mt][0] = Gu[base];
                    a[mt][1] = Gu[base + 8 * GSTR];
                    a[mt][2] = Gu[base + 4];
                    a[mt][3] = Gu[base + 8 * GSTR + 4];
                }
                const int brow = ((k0 >> 3) * 4 + (l & 3)) * MSTR2 + bcol;
                #pragma unroll
                for (int jt = 0; jt < 7; jt++) {
                    float2 bb = M2[brow + jt * 8];
                    uint32_t b0 = __float_as_uint(bb.x);
                    uint32_t b1 = __float_as_uint(bb.y);
                    mma_tf32(d[0][jt], a[0], b0, b1);
                    mma_tf32(d[1][jt], a[1], b0, b1);
                }
            }
        }

        // -------- stage C: two halves of 16 edges --------
        #pragma unroll
        for (int half = 0; half < 2; half++) {
            barg(g);   // prev tS reads done / stage-B Gs reads done
            {
                // all 4 warps stage their 56-col slice of this half's 16 rows
                #pragma unroll
                for (int jt = 0; jt < 7; jt++) {
                    int c = n0 + jt * 8 + (l & 3) * 2;
                    float c0 = cS[c], c1 = cS[c + 1];
                    int r0 = (l >> 2);
                    *(float2*)&tS[r0 * TSTR + c] =
                        make_float2(d[half][jt][0] + c0, d[half][jt][1] + c1);
                    *(float2*)&tS[(r0 + 8) * TSTR + c] =
                        make_float2(d[half][jt][2] + c0, d[half][jt][3] + c1);
                }
            }
            barg(g);

            // balanced coalesced scatter: 4 warps x 4 edges
            const float4 b0v = *(const float4*)&b0s[l * 4];
            #pragma unroll 1
            for (int i = 0; i < 4; i++) {
                const int er = wg * 4 + i;            // row in tS (0..15)
                const int e  = half * 16 + er;        // edge in tile
                if (e0 + e >= E) continue;
                const float* te = &tS[er * TSTR];
                const float* sh = &shP[e * 9];
                float* base = out + (size_t)dstP[e] * 480;
                const float s0 = sh[0];

                // region 0: cols 0..127, one red4 per lane
                {
                    float4 v = *(const float4*)&te[l * 4];
                    red4(base + l * 4,
                         fmaf(s0, v.x, b0v.x), fmaf(s0, v.y, b0v.y),
                         fmaf(s0, v.z, b0v.z), fmaf(s0, v.w, b0v.w));
                }
                // regions 1+2 merged: 88 quad-items in 3 rounds
                #pragma unroll
                for (int r = 0; r < 3; r++) {
                    int j = l + r * 32;
                    if (j < 88) {
                        int  r2   = (j >= 48);
                        int  jj   = r2 ? (j - 48) : j;
                        int  pidx = 4 * jj;
                        int  q    = r2 ? ((pidx * 0x3334) >> 16)
                                       : ((pidx * 0x5556) >> 16);
                        int  mod  = r2 ? 5 : 3;
                        int  m    = pidx - mod * q;
                        const float* tb_ = te + (r2 ? 192 : 128);
                        int  qb   = q + 1;
                        if (r2 && qb > 31) qb = 31;
                        float ta  = tb_[q];
                        float tbv = tb_[qb];
                        const float* shb = sh + (r2 ? 4 : 1);
                        float v[4];
                        #pragma unroll
                        for (int ii = 0; ii < 4; ii++) {
                            int mi = m + ii;
                            int f  = (mi >= mod);
                            float sv = shb[mi - mod * f];
                            v[ii] = (f ? tbv : ta) * sv;
                        }
                        red4(base + (r2 ? 320 : 128) + pidx, v[0], v[1], v[2], v[3]);
                    }
                }
            }
        }
        tCur = tNext;
        p ^= 1;
    }
}

// ---------------------------------------------------------------------------
extern "C" void kernel_launch(void* const* d_in, const int* in_sizes, int n_in,
                              void* d_out, int out_size) {
    const float* edge_attr    = (const float*)d_in[1];
    const float* edge_scalars = (const float*)d_in[2];
    const int*   edge_dst     = (const int*)d_in[4];
    const float* exp_w   = (const float*)d_in[6];
    const float* exp_b   = (const float*)d_in[7];
    const float* rad_w1  = (const float*)d_in[8];
    const float* rad_b1  = (const float*)d_in[9];
    const float* rad_gamma = (const float*)d_in[10];
    const float* rad_beta  = (const float*)d_in[11];
    const float* rad_w2  = (const float*)d_in[12];
    const float* rad_b2  = (const float*)d_in[13];
    const float* proj_w0 = (const float*)d_in[14];
    const float* proj_b0 = (const float*)d_in[15];
    const float* proj_w1 = (const float*)d_in[16];
    const float* proj_w2 = (const float*)d_in[17];
    float* out = (float*)d_out;
    const int E = in_sizes[4];

    int sms = 148;
    cudaDeviceGetAttribute(&sms, cudaDevAttrMultiProcessorCount, 0);
    const int nTiles = (E + 31) / 32;
    int grid = (nTiles + 3) / 4;
    if (grid > sms) grid = sms;

    // precompute + output zeroing fused + work-steal counter reset
    precompute_kernel<<<69 + ZBLOCKS, 1024>>>(exp_w, exp_b, rad_w2, rad_b2,
                                              proj_w0, proj_w1, proj_w2, rad_w1,
                                              out, out_size, grid * 4);

    const size_t SMEM_FLOATS = CONST_OFF + 64 * 3 + 256 + 128;   // 54608
    const size_t SMEM_BYTES = SMEM_FLOATS * sizeof(float);        // 218432
    cudaFuncSetAttribute(edge_main_kernel,
                         cudaFuncAttributeMaxDynamicSharedMemorySize, (int)SMEM_BYTES);

    edge_main_kernel<<<grid, THREADS, SMEM_BYTES>>>(
        edge_attr, edge_scalars, edge_dst,
        rad_b1, rad_gamma, rad_beta,
        proj_b0, out, E, nTiles);
}

// round 16
// speedup vs baseline: 1.0780x; 1.0019x over previous
#include <cuda_runtime.h>
#include <cuda_bf16.h>
#include <cstdint>

#define THREADS 512
#define RCOLS   224
#define MSTR2   228     // Ms row stride in float2 (mod 16 == 4 -> conflict-free LDS.64)
#define XSTR    68      // Xs row stride (mod 32 == 4 -> conflict-free A frags)
#define GSTR    68
#define W1STR2  68      // W1 row stride in float2 (mod 16 == 4)
#define TSTR    228     // t staging row stride (16 rows per half)

#define ZBLOCKS 256     // zeroing blocks appended to precompute launch

// group-local smem block sizes (floats)
#define GRP_FLOATS (2176 + 2176 + 3648 + 2*288 + 2*32 + 128 + 4)  // 8772
#define MS_FLOATS  (32 * MSTR2 * 2)                                // 14592
#define W1_FLOATS  (32 * W1STR2 * 2)                               // 4352
#define CONST_OFF  (MS_FLOATS + W1_FLOATS + 4 * GRP_FLOATS)        // 54032

// Precomputed fused weight M, row-pair packed:
//   g_M[(prow*224 + col)*2 + slot],  prow=(k>>3)*4+(k&3), slot=(k>>2)&1
// bias row c[256] (fp32), W1 packed the same way (64 cols).
__device__ __align__(16) float g_M[32 * 224 * 2];
__device__ __align__(16) float g_c[256];
__device__ __align__(16) float g_W1[32 * 64 * 2];
__device__ int g_tile_ctr;                 // work-stealing cursor

__device__ __forceinline__ uint32_t f2tf32(float f) {
    uint32_t u;
    asm("cvt.rna.tf32.f32 %0, %1;" : "=r"(u) : "f"(f));
    return u;
}

// ---------------------------------------------------------------------------
// Precompute + output zeroing in ONE launch.
// Blocks 0..64: M rows (64 = bias row). Blocks 65..68: W1 tf32 conversion.
// Blocks 69..69+ZBLOCKS-1: zero d_out (grid-strided float4).
// Block 0 thread 0 also resets the work-stealing counter.
// ---------------------------------------------------------------------------
__global__ __launch_bounds__(1024)
void precompute_kernel(const float* __restrict__ exp_w,
                       const float* __restrict__ exp_b,
                       const float* __restrict__ rad_w2,
                       const float* __restrict__ rad_b2,
                       const float* __restrict__ pw0,
                       const float* __restrict__ pw1,
                       const float* __restrict__ pw2,
                       const float* __restrict__ rad_w1,
                       float* __restrict__ out, int out_size,
                       int ctr_init) {
    int k = blockIdx.x;
    int tid = threadIdx.x;

    if (k == 0 && tid == 0) g_tile_ctr = ctr_init;

    if (k >= 69) {                       // output zeroing
        int zb = k - 69;
        float4* o4 = (float4*)out;
        int n4 = out_size >> 2;
        const float4 z = make_float4(0.f, 0.f, 0.f, 0.f);
        for (int i = zb * 1024 + tid; i < n4; i += ZBLOCKS * 1024)
            o4[i] = z;
        if (zb == 0 && tid < (out_size & 3))
            out[n4 * 4 + tid] = 0.f;
        return;
    }

    if (k >= 65) {                       // W1 conversion: 4 blocks x 1024
        int i = (k - 65) * 1024 + tid;
        if (i < 64 * 64) {
            int kk = i >> 6, col = i & 63;
            int prow = (kk >> 3) * 4 + (kk & 3);
            int slot = (kk >> 2) & 1;
            g_W1[prow * 128 + col * 2 + slot] = __uint_as_float(f2tf32(rad_w1[i]));
        }
        return;
    }

    __shared__ float s_s[128];
    __shared__ float s_w[384];
    __shared__ float part[4][256];

    if (tid < 128) s_s[tid] = exp_w[tid] + exp_b[tid];
    if (tid >= 128 && tid < 512) {
        int i = tid - 128;
        s_w[i] = (k < 64) ? rad_w2[k * 384 + i] : rad_b2[i];
    }
    __syncthreads();

    const int cs  = tid >> 8;    // 0..3: c chunk
    const int col = tid & 255;   // 0..255
    float acc = 0.f;
    if (col < RCOLS) {
        const float* P;
        int d, woff, pstride;
        if (col < 128)      { P = pw0; d = col;       woff = 0;   pstride = 128; }
        else if (col < 192) { P = pw1; d = col - 128; woff = 128; pstride = 64;  }
        else                { P = pw2; d = col - 192; woff = 256; pstride = 32;  }
        const int c0 = cs * 32;
        #pragma unroll 8
        for (int c = c0; c < c0 + 32; c++)
            acc += s_w[woff + c] * s_s[c] * __ldg(&P[c * pstride + d]);
    }
    part[cs][col] = acc;
    __syncthreads();

    if (tid < 256) {
        float sum = (part[0][tid] + part[1][tid]) + (part[2][tid] + part[3][tid]);
        sum *= 0.25f;   // 1/sqrt(AVG_AGG)
        if (k < 64) {
            if (tid < RCOLS) {
                int prow = (k >> 3) * 4 + (k & 3);
                int slot = (k >> 2) & 1;
                g_M[(prow * 224 + tid) * 2 + slot] = __uint_as_float(f2tf32(sum));
            }
        } else {
            g_c[tid] = sum;
        }
    }
}

// ---------------------------------------------------------------------------
__device__ __forceinline__ void red4(float* p, float a, float b, float c, float d) {
    asm volatile("red.global.add.v4.f32 [%0], {%1, %2, %3, %4};"
                 :: "l"(p), "f"(a), "f"(b), "f"(c), "f"(d) : "memory");
}

__device__ __forceinline__ void cp_async16(void* smem_ptr, const void* gmem) {
    uint32_t s = (uint32_t)__cvta_generic_to_shared(smem_ptr);
    asm volatile("cp.async.cg.shared.global [%0], [%1], 16;" :: "r"(s), "l"(gmem));
}
__device__ __forceinline__ void cp_async16_zfill(void* smem_ptr, const void* gmem, int srcsz) {
    uint32_t s = (uint32_t)__cvta_generic_to_shared(smem_ptr);
    asm volatile("cp.async.cg.shared.global [%0], [%1], 16, %2;"
                 :: "r"(s), "l"(gmem), "r"(srcsz));
}

__device__ __forceinline__ void mma_tf32(float d[4], const uint32_t a[4],
                                         uint32_t b0, uint32_t b1) {
    asm volatile(
        "mma.sync.aligned.m16n8k8.row.col.f32.tf32.tf32.f32 "
        "{%0,%1,%2,%3}, {%4,%5,%6,%7}, {%8,%9}, {%0,%1,%2,%3};"
        : "+f"(d[0]), "+f"(d[1]), "+f"(d[2]), "+f"(d[3])
        : "r"(a[0]), "r"(a[1]), "r"(a[2]), "r"(a[3]), "r"(b0), "r"(b1));
}

// group barrier (named): 128 threads of group g
__device__ __forceinline__ void barg(int g) {
    asm volatile("bar.sync %0, %1;" :: "r"(g + 1), "r"(128) : "memory");
}

// ---------------------------------------------------------------------------
// Persistent kernel, FOUR independent 128-thread warp-groups per CTA.
// Each group takes its first 32-edge tile statically, then steals the rest
// from a global cursor (removes static tail imbalance).
// ---------------------------------------------------------------------------
__global__ __launch_bounds__(THREADS, 1)
void edge_main_kernel(const float* __restrict__ edge_attr,
                      const float* __restrict__ edge_scalars,
                      const int*   __restrict__ edge_dst,
                      const float* __restrict__ rad_b1,
                      const float* __restrict__ rad_gamma,
                      const float* __restrict__ rad_beta,
                      const float* __restrict__ proj_b0,
                      float* __restrict__ out,
                      int E, int nTiles)
{
    extern __shared__ float smem[];
    float* Ms   = smem;                     // 14592 (32 x 228 float2)
    float* W1s  = Ms + MS_FLOATS;           // 4352  (32 x 68 float2)
    // constants
    float* b1s  = smem + CONST_OFF;         // 64
    float* gms  = b1s + 64;                 // 64
    float* bts  = gms + 64;                 // 64
    float* cS   = bts + 64;                 // 256
    float* b0s  = cS + 256;                 // 128

    const int tid = threadIdx.x;
    const int g   = tid >> 7;        // warp-group 0..3
    const int gt  = tid & 127;       // thread-in-group
    const int l   = tid & 31;
    const int wg  = (tid >> 5) & 3;  // warp-in-group 0..3

    // group-local buffers
    float* GB   = smem + MS_FLOATS + W1_FLOATS + g * GRP_FLOATS;
    float* Xs   = GB;                       // 32*68 = 2176
    float* Gs   = Xs + 2176;                // 32*68 = 2176
    float* tS   = Gs + 2176;                // 16*228 = 3648
    float* sh0  = tS + 3648;                // 288
    float* sh1  = sh0 + 288;                // 288
    int*   dst0 = (int*)(sh1 + 288);        // 32
    int*   dst1 = dst0 + 32;                // 32
    float* pbuf = (float*)(dst1 + 32);      // 128
    int*   nextS = (int*)(pbuf + 128);      // 1 (+3 pad)

    // -------- one-time loads (all 512 threads): M, W1, constants --------
    for (int i = tid; i < 32 * 112; i += THREADS) {
        int row = i / 112, c4 = i - row * 112;
        cp_async16(&Ms[row * (MSTR2 * 2) + c4 * 4], &g_M[row * 448 + c4 * 4]);
    }
    for (int i = tid; i < 32 * 32; i += THREADS) {
        int row = i >> 5, c4 = i & 31;
        cp_async16(&W1s[row * (W1STR2 * 2) + c4 * 4], &g_W1[row * 128 + c4 * 4]);
    }
    if (tid < 64) { b1s[tid] = rad_b1[tid]; gms[tid] = rad_gamma[tid]; bts[tid] = rad_beta[tid]; }
    if (tid >= 64 && tid < 64 + 256) cS[tid - 64] = g_c[tid - 64];
    if (tid >= 320 && tid < 448) b0s[tid - 320] = proj_b0[tid - 320] * 0.25f;

    // -------- per-group tile prefetch (32 edges) --------
    auto prefetch = [&](int e0, float* shB, int* dstB) {
        if (e0 + 32 <= E) {   // full tile: no bounds math
            const float* xg = edge_scalars + (size_t)e0 * 64;
            #pragma unroll
            for (int r = 0; r < 4; r++) {
                int i = gt + r * 128;            // 0..511
                int e = i >> 4, c4 = i & 15;
                cp_async16(&Xs[e * XSTR + c4 * 4], xg + e * 64 + c4 * 4);
            }
            if (gt < 72)
                cp_async16(&shB[gt * 4], edge_attr + (size_t)e0 * 9 + gt * 4);
            if (gt < 8)
                cp_async16(&dstB[gt * 4], edge_dst + e0 + gt * 4);
        } else {
            #pragma unroll
            for (int r = 0; r < 4; r++) {
                int i = gt + r * 128;
                int e = i >> 4, c4 = i & 15;
                int ge = e0 + e;
                int gc = (ge < E) ? ge : (E - 1);
                cp_async16_zfill(&Xs[e * XSTR + c4 * 4],
                                 edge_scalars + (size_t)gc * 64 + c4 * 4,
                                 (ge < E) ? 16 : 0);
            }
            if (gt < 72) {
                long rem = (long)E * 9 - (long)e0 * 9 - (long)gt * 4;
                int sz = (rem >= 4) ? 16 : ((rem > 0) ? (int)(rem * 4) : 0);
                cp_async16_zfill(&shB[gt * 4], edge_attr + (size_t)e0 * 9 + gt * 4, sz);
            }
            if (gt < 8) {
                int off = gt * 4;
                int ge = e0 + off;
                int gc = (ge + 3 < E) ? ge : ((E >= 4) ? E - 4 : 0);
                int rem = E - ge;
                int sz = (rem >= 4) ? 16 : ((rem > 0) ? rem * 4 : 0);
                cp_async16_zfill(&dstB[off], edge_dst + gc, sz);
            }
        }
    };

    int tCur = blockIdx.x * 4 + g;   // first tile static
    if (tCur < nTiles) prefetch(tCur * 32, sh0, dst0);
    asm volatile("cp.async.commit_group;" ::: "memory");
    __syncthreads();   // constants visible; groups diverge after this

    int p = 0;
    while (tCur < nTiles) {
        const int e0 = tCur * 32;
        float* shP  = p ? sh1 : sh0;
        int*   dstP = p ? dst1 : dst0;

        asm volatile("cp.async.wait_group 0;" ::: "memory");
        barg(g);

        int tNext;
        // -------- stage A: h[32x64] = X @ W1 (mma tf32), LN fused --------
        {
            const int mt = wg >> 1;          // 0..1
            const int nq = wg & 1;
            const int m0 = mt * 16;
            float d[4][4] = {};
            const int ar0 = (m0 + (l >> 2)) * XSTR + (l & 3);
            const int ar1 = ar0 + 8 * XSTR;
            const float2* W2 = (const float2*)W1s;
            const int wcol = nq * 32 + (l >> 2);   // float2 col base

            #pragma unroll
            for (int k0 = 0; k0 < 64; k0 += 8) {
                uint32_t a[4];
                a[0] = f2tf32(Xs[ar0 + k0]);
                a[1] = f2tf32(Xs[ar1 + k0]);
                a[2] = f2tf32(Xs[ar0 + k0 + 4]);
                a[3] = f2tf32(Xs[ar1 + k0 + 4]);
                const int wrow = ((k0 >> 3) * 4 + (l & 3)) * W1STR2 + wcol;
                #pragma unroll
                for (int nt = 0; nt < 4; nt++) {
                    float2 bb = W2[wrow + nt * 8];
                    mma_tf32(d[nt], a, __float_as_uint(bb.x), __float_as_uint(bb.y));
                }
            }

            // bias + per-row partial sums over this warp's 32 cols
            float ps0 = 0.f, pq0 = 0.f, ps1 = 0.f, pq1 = 0.f;
            #pragma unroll
            for (int nt = 0; nt < 4; nt++) {
                int c = nq * 32 + nt * 8 + (l & 3) * 2;
                float b0 = b1s[c], b1 = b1s[c + 1];
                d[nt][0] += b0; d[nt][1] += b1;
                d[nt][2] += b0; d[nt][3] += b1;
                ps0 += d[nt][0] + d[nt][1];
                pq0 += d[nt][0] * d[nt][0] + d[nt][1] * d[nt][1];
                ps1 += d[nt][2] + d[nt][3];
                pq1 += d[nt][2] * d[nt][2] + d[nt][3] * d[nt][3];
            }
            #pragma unroll
            for (int o = 1; o <= 2; o <<= 1) {
                ps0 += __shfl_xor_sync(0xffffffffu, ps0, o);
                pq0 += __shfl_xor_sync(0xffffffffu, pq0, o);
                ps1 += __shfl_xor_sync(0xffffffffu, ps1, o);
                pq1 += __shfl_xor_sync(0xffffffffu, pq1, o);
            }
            if ((l & 3) == 0)
                *(float4*)&pbuf[(wg * 8 + (l >> 2)) * 4] = make_float4(ps0, pq0, ps1, pq1);
            // steal next tile (one thread per group)
            if (gt == 0) nextS[0] = atomicAdd(&g_tile_ctr, 1);
            barg(g);   // partials + nextS visible; ALL stage-A Xs reads done

            // prefetch next tile (Xs now free)
            tNext = nextS[0];
            if (tNext < nTiles) prefetch(tNext * 32, p ? sh0 : sh1, p ? dst0 : dst1);
            asm volatile("cp.async.commit_group;" ::: "memory");

            // merge partner warp's partials -> full 64-col row stats
            float4 pp = *(const float4*)&pbuf[((wg ^ 1) * 8 + (l >> 2)) * 4];
            ps0 += pp.x; pq0 += pp.y; ps1 += pp.z; pq1 += pp.w;
            float mu0   = ps0 * (1.f / 64.f);
            float rstd0 = rsqrtf(pq0 * (1.f / 64.f) - mu0 * mu0 + 1e-5f);
            float mu1   = ps1 * (1.f / 64.f);
            float rstd1 = rsqrtf(pq1 * (1.f / 64.f) - mu1 * mu1 + 1e-5f);

            // normalize + silu + tf32, store G
            const int r0 = m0 + (l >> 2);
            #pragma unroll
            for (int nt = 0; nt < 4; nt++) {
                int c = nq * 32 + nt * 8 + (l & 3) * 2;
                float g0 = gms[c], g1 = gms[c + 1];
                float q0 = bts[c], q1 = bts[c + 1];
                float v00 = (d[nt][0] - mu0) * rstd0 * g0 + q0;
                float v01 = (d[nt][1] - mu0) * rstd0 * g1 + q1;
                float v10 = (d[nt][2] - mu1) * rstd1 * g0 + q0;
                float v11 = (d[nt][3] - mu1) * rstd1 * g1 + q1;
                v00 = __fdividef(v00, 1.f + __expf(-v00));
                v01 = __fdividef(v01, 1.f + __expf(-v01));
                v10 = __fdividef(v10, 1.f + __expf(-v10));
                v11 = __fdividef(v11, 1.f + __expf(-v11));
                *(uint2*)&Gs[r0 * GSTR + c]       = make_uint2(f2tf32(v00), f2tf32(v01));
                *(uint2*)&Gs[(r0 + 8) * GSTR + c] = make_uint2(f2tf32(v10), f2tf32(v11));
            }
        }
        barg(g);   // G visible to group

        // -------- stage B: t[32x224] = G @ M + c (mma tf32) --------
        // each warp: all 32 rows x 56 cols (n0 = wg*56)
        float d[2][7][4] = {};
        const int n0 = wg * 56;
        {
            const uint32_t* Gu = (const uint32_t*)Gs;
            const float2* M2 = (const float2*)Ms;
            const int ar00 = (l >> 2) * GSTR + (l & 3);
            const int bcol = n0 + (l >> 2);

            #pragma unroll
            for (int k0 = 0; k0 < 64; k0 += 8) {
                uint32_t a[2][4];
                #pragma unroll
                for (int mt = 0; mt < 2; mt++) {
                    int base = ar00 + mt * 16 * GSTR + k0;
                    a[mt][0] = Gu[base];
                    a[mt][1] = Gu[base + 8 * GSTR];
                    a[mt][2] = Gu[base + 4];
                    a[mt][3] = Gu[base + 8 * GSTR + 4];
                }
                const int brow = ((k0 >> 3) * 4 + (l & 3)) * MSTR2 + bcol;
                #pragma unroll
                for (int jt = 0; jt < 7; jt++) {
                    float2 bb = M2[brow + jt * 8];
                    uint32_t b0 = __float_as_uint(bb.x);
                    uint32_t b1 = __float_as_uint(bb.y);
                    mma_tf32(d[0][jt], a[0], b0, b1);
                    mma_tf32(d[1][jt], a[1], b0, b1);
                }
            }
        }

        // -------- stage C: two halves of 16 edges --------
        #pragma unroll
        for (int half = 0; half < 2; half++) {
            barg(g);   // prev tS reads done / stage-B Gs reads done
            {
                // all 4 warps stage their 56-col slice of this half's 16 rows
                #pragma unroll
                for (int jt = 0; jt < 7; jt++) {
                    int c = n0 + jt * 8 + (l & 3) * 2;
                    float c0 = cS[c], c1 = cS[c + 1];
                    int r0 = (l >> 2);
                    *(float2*)&tS[r0 * TSTR + c] =
                        make_float2(d[half][jt][0] + c0, d[half][jt][1] + c1);
                    *(float2*)&tS[(r0 + 8) * TSTR + c] =
                        make_float2(d[half][jt][2] + c0, d[half][jt][3] + c1);
                }
            }
            barg(g);

            // balanced coalesced scatter: 4 warps x 4 edges
            const float4 b0v = *(const float4*)&b0s[l * 4];
            #pragma unroll 1
            for (int i = 0; i < 4; i++) {
                const int er = wg * 4 + i;            // row in tS (0..15)
                const int e  = half * 16 + er;        // edge in tile
                if (e0 + e >= E) continue;
                const float* te = &tS[er * TSTR];
                const float* sh = &shP[e * 9];
                float* base = out + (size_t)dstP[e] * 480;
                const float s0 = sh[0];

                // region 0: cols 0..127, one red4 per lane
                {
                    float4 v = *(const float4*)&te[l * 4];
                    red4(base + l * 4,
                         fmaf(s0, v.x, b0v.x), fmaf(s0, v.y, b0v.y),
                         fmaf(s0, v.z, b0v.z), fmaf(s0, v.w, b0v.w));
                }
                // regions 1+2 merged: 88 quad-items in 3 rounds
                #pragma unroll
                for (int r = 0; r < 3; r++) {
                    int j = l + r * 32;
                    if (j < 88) {
                        int  r2   = (j >= 48);
                        int  jj   = r2 ? (j - 48) : j;
                        int  pidx = 4 * jj;
                        int  q    = r2 ? ((pidx * 0x3334) >> 16)
                                       : ((pidx * 0x5556) >> 16);
                        int  mod  = r2 ? 5 : 3;
                        int  m    = pidx - mod * q;
                        const float* tb_ = te + (r2 ? 192 : 128);
                        int  qb   = q + 1;
                        if (r2 && qb > 31) qb = 31;
                        float ta  = tb_[q];
                        float tbv = tb_[qb];
                        const float* shb = sh + (r2 ? 4 : 1);
                        float v[4];
                        #pragma unroll
                        for (int ii = 0; ii < 4; ii++) {
                            int mi = m + ii;
                            int f  = (mi >= mod);
                            float sv = shb[mi - mod * f];
                            v[ii] = (f ? tbv : ta) * sv;
                        }
                        red4(base + (r2 ? 320 : 128) + pidx, v[0], v[1], v[2], v[3]);
                    }
                }
            }
        }
        tCur = tNext;
        p ^= 1;
    }
}

// ---------------------------------------------------------------------------
extern "C" void kernel_launch(void* const* d_in, const int* in_sizes, int n_in,
                              void* d_out, int out_size) {
    const float* edge_attr    = (const float*)d_in[1];
    const float* edge_scalars = (const float*)d_in[2];
    const int*   edge_dst     = (const int*)d_in[4];
    const float* exp_w   = (const float*)d_in[6];
    const float* exp_b   = (const float*)d_in[7];
    const float* rad_w1  = (const float*)d_in[8];
    const float* rad_b1  = (const float*)d_in[9];
    const float* rad_gamma = (const float*)d_in[10];
    const float* rad_beta  = (const float*)d_in[11];
    const float* rad_w2  = (const float*)d_in[12];
    const float* rad_b2  = (const float*)d_in[13];
    const float* proj_w0 = (const float*)d_in[14];
    const float* proj_b0 = (const float*)d_in[15];
    const float* proj_w1 = (const float*)d_in[16];
    const float* proj_w2 = (const float*)d_in[17];
    float* out = (float*)d_out;
    const int E = in_sizes[4];

    int sms = 148;
    cudaDeviceGetAttribute(&sms, cudaDevAttrMultiProcessorCount, 0);
    const int nTiles = (E + 31) / 32;
    int grid = (nTiles + 3) / 4;
    if (grid > sms) grid = sms;

    // precompute + output zeroing fused + work-steal counter reset
    precompute_kernel<<<69 + ZBLOCKS, 1024>>>(exp_w, exp_b, rad_w2, rad_b2,
                                              proj_w0, proj_w1, proj_w2, rad_w1,
                                              out, out_size, grid * 4);

    const size_t SMEM_FLOATS = CONST_OFF + 64 * 3 + 256 + 128;   // 54608
    const size_t SMEM_BYTES = SMEM_FLOATS * sizeof(float);        // 218432
    cudaFuncSetAttribute(edge_main_kernel,
                         cudaFuncAttributeMaxDynamicSharedMemorySize, (int)SMEM_BYTES);

    edge_main_kernel<<<grid, THREADS, SMEM_BYTES>>>(
        edge_attr, edge_scalars, edge_dst,
        rad_b1, rad_gamma, rad_beta,
        proj_b0, out, E, nTiles);
}